// round 4
// baseline (speedup 1.0000x reference)
#include <cuda_runtime.h>

#define MROWS   512   // rows of weight / output dim
#define KDIM    20    // motion dim
#define OUT_DIM 512
#define BTILE   256   // batch rows per block in GEMM
#define GTHREADS 128  // 4 warps: 128 threads x 4 outputs = 512 outputs

// Q transposed: g_Qt[k*512 + o] = Q[o][k]
__device__ float g_Qt[KDIM * OUT_DIM];

// ---------------------------------------------------------------------------
// helpers
// ---------------------------------------------------------------------------
__device__ __forceinline__ float blockReduceSum(float x, float* red) {
    int lane = threadIdx.x & 31;
    int wid  = threadIdx.x >> 5;
    #pragma unroll
    for (int off = 16; off; off >>= 1) x += __shfl_xor_sync(0xffffffffu, x, off);
    if (lane == 0) red[wid] = x;
    __syncthreads();
    float s = (lane < 16) ? red[lane] : 0.f;   // 16 warps -> 16 partials
    #pragma unroll
    for (int off = 8; off; off >>= 1) s += __shfl_xor_sync(0xffffffffu, s, off);
    s = __shfl_sync(0xffffffffu, s, 0);
    __syncthreads();                            // protect red for next call
    return s;
}

__device__ __forceinline__ unsigned long long pack2(float lo, float hi) {
    unsigned long long r;
    asm("mov.b64 %0, {%1, %2};" : "=l"(r) : "f"(lo), "f"(hi));
    return r;
}

__device__ __forceinline__ unsigned long long ffma2(unsigned long long a,
                                                    unsigned long long b,
                                                    unsigned long long c) {
    unsigned long long d;
    asm("fma.rn.f32x2 %0, %1, %2, %3;" : "=l"(d) : "l"(a), "l"(b), "l"(c));
    return d;
}

__device__ __forceinline__ float hadd2(unsigned long long a) {
    float lo, hi;
    asm("mov.b64 {%0, %1}, %2;" : "=f"(lo), "=f"(hi) : "l"(a));
    return lo + hi;
}

// ---------------------------------------------------------------------------
// Householder QR (LAPACK sgeqr2 + sorg2r conventions) of W + 1e-8, W: [512,20]
// Single block, 512 threads (one per row). Writes Q^T to g_Qt.
// ---------------------------------------------------------------------------
__global__ void qr_kernel(const float* __restrict__ W) {
    __shared__ float sA[KDIM][MROWS];   // column-major: sA[c][t] = A[t][c]
    __shared__ float sV[MROWS];
    __shared__ float sTau[KDIM];
    __shared__ float sRed[16];

    const int t    = threadIdx.x;
    const int lane = t & 31;
    const int wid  = t >> 5;

    #pragma unroll
    for (int c = 0; c < KDIM; ++c)
        sA[c][t] = W[t * KDIM + c] + 1e-8f;
    __syncthreads();

    // ---- factorization (geqr2) ----
    for (int j = 0; j < KDIM; ++j) {
        float a  = sA[j][t];
        float sq = (t > j) ? a * a : 0.f;
        float xnorm2 = blockReduceSum(sq, sRed);
        float alpha  = sA[j][j];
        float beta   = -copysignf(sqrtf(alpha * alpha + xnorm2), alpha); // LAPACK sign
        float tau    = (beta - alpha) / beta;
        float inv    = 1.f / (alpha - beta);
        float v      = (t == j) ? 1.f : ((t > j) ? a * inv : 0.f);
        sV[t] = v;
        if (t == j)      { sTau[j] = tau; sA[j][j] = beta; }
        else if (t > j)  { sA[j][t] = v; }   // store reflector
        __syncthreads();

        // trailing update: one warp per column
        for (int c = j + 1 + wid; c < KDIM; c += 16) {
            float w = 0.f;
            #pragma unroll
            for (int i = lane; i < MROWS; i += 32) w += sV[i] * sA[c][i];
            #pragma unroll
            for (int off = 16; off; off >>= 1) w += __shfl_xor_sync(0xffffffffu, w, off);
            float tw = sTau[j] * w;
            #pragma unroll
            for (int i = lane; i < MROWS; i += 32) sA[c][i] -= tw * sV[i];
        }
        __syncthreads();
    }

    // ---- form Q in place (org2r) ----
    for (int j = KDIM - 1; j >= 0; --j) {
        float tau = sTau[j];
        float vt  = (t == j) ? 1.f : ((t > j) ? sA[j][t] : 0.f);
        sV[t] = vt;
        __syncthreads();

        for (int c = j + 1 + wid; c < KDIM; c += 16) {
            float w = 0.f;
            #pragma unroll
            for (int i = lane; i < MROWS; i += 32) w += sV[i] * sA[c][i];
            #pragma unroll
            for (int off = 16; off; off >>= 1) w += __shfl_xor_sync(0xffffffffu, w, off);
            float tw = tau * w;
            #pragma unroll
            for (int i = lane; i < MROWS; i += 32) sA[c][i] -= tw * sV[i];
        }
        __syncthreads();
        sA[j][t] = (t == j) ? (1.f - tau) : ((t > j) ? -tau * vt : 0.f);
        __syncthreads();
    }

    // store Q^T (coalesced per column)
    #pragma unroll
    for (int k = 0; k < KDIM; ++k)
        g_Qt[k * OUT_DIM + t] = sA[k][t];
}

// ---------------------------------------------------------------------------
// out[b][o] = sum_k input[b][k] * Q[o][k]
// 128 threads, 4 outputs/thread. Q register-resident, paired along k.
// Per thread-row: 5 LDS.128 (broadcast), 40 FFMA2, 4 FADD, 1 STG.128.
// __launch_bounds__(128,5) caps regs at 102 -> 5 CTAs/SM for latency hiding.
// ---------------------------------------------------------------------------
__global__ void __launch_bounds__(GTHREADS, 5)
gemm_kernel(const float* __restrict__ input, float* __restrict__ out, int batch) {
    __shared__ float sIn[BTILE * KDIM];   // 20 KB

    const int tid = threadIdx.x;
    const long long b0 = (long long)blockIdx.x * BTILE;
    const int rows = (batch - b0 < BTILE) ? (int)(batch - b0) : BTILE;

    // this thread's Q columns (o = 4*tid .. 4*tid+3), paired along k
    unsigned long long q0[KDIM / 2], q1[KDIM / 2], q2[KDIM / 2], q3[KDIM / 2];
    #pragma unroll
    for (int p = 0; p < KDIM / 2; ++p) {
        float4 e = reinterpret_cast<const float4*>(g_Qt + (2 * p)     * OUT_DIM)[tid];
        float4 o = reinterpret_cast<const float4*>(g_Qt + (2 * p + 1) * OUT_DIM)[tid];
        q0[p] = pack2(e.x, o.x);
        q1[p] = pack2(e.y, o.y);
        q2[p] = pack2(e.z, o.z);
        q3[p] = pack2(e.w, o.w);
    }

    // stage input tile (raw copy, float4-vectorized)
    const float4* inBlk = reinterpret_cast<const float4*>(input + b0 * KDIM);
    float4* sIn4 = reinterpret_cast<float4*>(sIn);
    const int n4 = rows * KDIM / 4;            // rows*5 float4s
    for (int i = tid; i < n4; i += GTHREADS) {
        sIn4[i] = inBlk[i];
    }
    __syncthreads();

    float4* outp = reinterpret_cast<float4*>(out + b0 * OUT_DIM) + tid;

    #pragma unroll 4
    for (int r = 0; r < rows; ++r) {
        const ulonglong2* row = reinterpret_cast<const ulonglong2*>(sIn + r * KDIM);
        unsigned long long acc0 = 0ull, acc1 = 0ull, acc2 = 0ull, acc3 = 0ull;
        #pragma unroll
        for (int p = 0; p < KDIM / 4; ++p) {   // 5 LDS.128, all-lane broadcast
            ulonglong2 x = row[p];
            acc0 = ffma2(x.x, q0[2 * p],     acc0);
            acc1 = ffma2(x.x, q1[2 * p],     acc1);
            acc2 = ffma2(x.x, q2[2 * p],     acc2);
            acc3 = ffma2(x.x, q3[2 * p],     acc3);
            acc0 = ffma2(x.y, q0[2 * p + 1], acc0);
            acc1 = ffma2(x.y, q1[2 * p + 1], acc1);
            acc2 = ffma2(x.y, q2[2 * p + 1], acc2);
            acc3 = ffma2(x.y, q3[2 * p + 1], acc3);
        }
        float4 res;
        res.x = hadd2(acc0);
        res.y = hadd2(acc1);
        res.z = hadd2(acc2);
        res.w = hadd2(acc3);
        outp[r * (OUT_DIM / 4)] = res;         // out[(b0+r)*512 + 4*tid]
    }
}

// ---------------------------------------------------------------------------
extern "C" void kernel_launch(void* const* d_in, const int* in_sizes, int n_in,
                              void* d_out, int out_size) {
    const float* input  = (const float*)d_in[0];
    const float* weight = (const float*)d_in[1];
    int s0 = in_sizes[0], s1 = in_sizes[1];
    if (s0 < s1) {  // weight is the smaller tensor (512*20); be robust to order
        const float* tmp = input; input = weight; weight = tmp;
        int ts = s0; s0 = s1; s1 = ts;
    }
    const int batch = s0 / KDIM;

    qr_kernel<<<1, MROWS>>>(weight);

    const int grid = (batch + BTILE - 1) / BTILE;
    gemm_kernel<<<grid, GTHREADS>>>(input, (float*)d_out, batch);
}

// round 6
// speedup vs baseline: 1.0218x; 1.0218x over previous
#include <cuda_runtime.h>
#include <cuda_bf16.h>
#include <cstdint>

#define MROWS   512   // rows of weight / output dim
#define KDIM    20    // motion dim
#define OUT_DIM 512
#define TILE_M  128   // batch rows per block
#define KPAD    64    // split-K layout: A=[hi20|lo20|hi20|0], B=[hi20|hi20|lo20|0]
#define GTHREADS 256  // 8 warps, each owns 64 output cols
#define SROW_W  36    // smem row stride in 32-bit words (72 bf16) -> conflict-free frags

// B' table (bf16): g_Qbf[n*64 + k]; k 0-19 = Qhi, 20-39 = Qhi, 40-59 = Qlo, 60-63 = 0
__device__ __align__(16) __nv_bfloat16 g_Qbf[OUT_DIM * KPAD];

// ---------------------------------------------------------------------------
// helpers
// ---------------------------------------------------------------------------
__device__ __forceinline__ uint32_t bf2pack(float a, float b) {
    __nv_bfloat162 t = __floats2bfloat162_rn(a, b);   // x = a (low), y = b (high)
    return *reinterpret_cast<uint32_t*>(&t);
}

__device__ __forceinline__ float blockReduceSum(float x, float* red) {
    int lane = threadIdx.x & 31;
    int wid  = threadIdx.x >> 5;
    #pragma unroll
    for (int off = 16; off; off >>= 1) x += __shfl_xor_sync(0xffffffffu, x, off);
    if (lane == 0) red[wid] = x;
    __syncthreads();
    float s = (lane < 16) ? red[lane] : 0.f;
    #pragma unroll
    for (int off = 8; off; off >>= 1) s += __shfl_xor_sync(0xffffffffu, s, off);
    s = __shfl_sync(0xffffffffu, s, 0);
    __syncthreads();
    return s;
}

// m16n8k16 bf16 MMA, fp32 accum (standard PTX, no sm_103a-gated features)
__device__ __forceinline__ void mma16816(float* d,
                                         uint32_t a0, uint32_t a1, uint32_t a2, uint32_t a3,
                                         uint32_t b0, uint32_t b1) {
    asm("mma.sync.aligned.m16n8k16.row.col.f32.bf16.bf16.f32 "
        "{%0,%1,%2,%3}, {%4,%5,%6,%7}, {%8,%9}, {%0,%1,%2,%3};"
        : "+f"(d[0]), "+f"(d[1]), "+f"(d[2]), "+f"(d[3])
        : "r"(a0), "r"(a1), "r"(a2), "r"(a3), "r"(b0), "r"(b1));
}

// ---------------------------------------------------------------------------
// Householder QR (LAPACK sgeqr2 + sorg2r) of W + 1e-8, W: [512,20].
// Emits bf16 hi/lo split table g_Qbf (B layout: [qh|qh|ql|0]).
// ---------------------------------------------------------------------------
__global__ void qr_kernel(const float* __restrict__ W) {
    __shared__ float sA[KDIM][MROWS];
    __shared__ float sV[MROWS];
    __shared__ float sTau[KDIM];
    __shared__ float sRed[16];

    const int t    = threadIdx.x;
    const int lane = t & 31;
    const int wid  = t >> 5;

    #pragma unroll
    for (int c = 0; c < KDIM; ++c)
        sA[c][t] = W[t * KDIM + c] + 1e-8f;
    __syncthreads();

    for (int j = 0; j < KDIM; ++j) {
        float a  = sA[j][t];
        float sq = (t > j) ? a * a : 0.f;
        float xnorm2 = blockReduceSum(sq, sRed);
        float alpha  = sA[j][j];
        float beta   = -copysignf(sqrtf(alpha * alpha + xnorm2), alpha);
        float tau    = (beta - alpha) / beta;
        float inv    = 1.f / (alpha - beta);
        float v      = (t == j) ? 1.f : ((t > j) ? a * inv : 0.f);
        sV[t] = v;
        if (t == j)      { sTau[j] = tau; sA[j][j] = beta; }
        else if (t > j)  { sA[j][t] = v; }
        __syncthreads();

        for (int c = j + 1 + wid; c < KDIM; c += 16) {
            float w = 0.f;
            #pragma unroll
            for (int i = lane; i < MROWS; i += 32) w += sV[i] * sA[c][i];
            #pragma unroll
            for (int off = 16; off; off >>= 1) w += __shfl_xor_sync(0xffffffffu, w, off);
            float tw = sTau[j] * w;
            #pragma unroll
            for (int i = lane; i < MROWS; i += 32) sA[c][i] -= tw * sV[i];
        }
        __syncthreads();
    }

    for (int j = KDIM - 1; j >= 0; --j) {
        float tau = sTau[j];
        float vt  = (t == j) ? 1.f : ((t > j) ? sA[j][t] : 0.f);
        sV[t] = vt;
        __syncthreads();

        for (int c = j + 1 + wid; c < KDIM; c += 16) {
            float w = 0.f;
            #pragma unroll
            for (int i = lane; i < MROWS; i += 32) w += sV[i] * sA[c][i];
            #pragma unroll
            for (int off = 16; off; off >>= 1) w += __shfl_xor_sync(0xffffffffu, w, off);
            float tw = tau * w;
            #pragma unroll
            for (int i = lane; i < MROWS; i += 32) sA[c][i] -= tw * sV[i];
        }
        __syncthreads();
        sA[j][t] = (t == j) ? (1.f - tau) : ((t > j) ? -tau * vt : 0.f);
        __syncthreads();
    }

    // bf16 split: row n = t; k[0,20)=Qhi, [20,40)=Qhi, [40,60)=Qlo, [60,64)=0
    #pragma unroll
    for (int k = 0; k < KDIM; ++k) {
        float q = sA[k][t];
        __nv_bfloat16 h = __float2bfloat16_rn(q);
        float lo = q - __bfloat162float(h);
        g_Qbf[t * KPAD + k]            = h;
        g_Qbf[t * KPAD + KDIM + k]     = h;
        g_Qbf[t * KPAD + 2 * KDIM + k] = __float2bfloat16_rn(lo);
    }
    #pragma unroll
    for (int k = 3 * KDIM; k < KPAD; ++k)
        g_Qbf[t * KPAD + k] = __float2bfloat16_rn(0.f);
}

// ---------------------------------------------------------------------------
// HMMA GEMM: out[b][o] = sum_k input[b][k] * Q[o][k]  (split bf16, fp32 acc)
// Block: 128 rows x 512 cols. 8 warps, warp w owns cols [64w, 64w+64).
// B fragments register-resident (64 u32). A converted once into smem bf16
// tile (row stride 36 words -> conflict-free fragment gathers).
// ---------------------------------------------------------------------------
__global__ void __launch_bounds__(GTHREADS, 2)
gemm_hmma_kernel(const float* __restrict__ input, float* __restrict__ out,
                 int batch) {
    __shared__ uint32_t sW[TILE_M * SROW_W];   // 18432 B

    const int tid  = threadIdx.x;
    const int wid  = tid >> 5;
    const int lane = tid & 31;
    const int g    = lane >> 2;        // fragment row group 0..7
    const int cq   = lane & 3;         // quad col: k pair base = 2*cq
    const long long tb = (long long)blockIdx.x * TILE_M;

    // ---- B fragments: B[j][t] = (B'[k=2cq+8t, n], B'[k+1, n]), n = 64w+8j+g ----
    uint32_t Bf[8][8];
    {
        const uint32_t* qw = reinterpret_cast<const uint32_t*>(g_Qbf);
        const int nb = wid * 64 + g;
        #pragma unroll
        for (int j = 0; j < 8; ++j) {
            const uint32_t* qrow = qw + (nb + 8 * j) * (KPAD / 2) + cq;
            #pragma unroll
            for (int t = 0; t < 8; ++t)
                Bf[j][t] = qrow[4 * t];
        }
    }

    // ---- convert input tile -> smem bf16 [hi20|lo20|hi20|0] per row ----
    {
        const int r  = tid >> 1;                // row 0..127
        const int h  = tid & 1;                 // half: k0 = 10h
        const long long grow = tb + r;
        float2 v[5];
        if (grow < batch) {
            const float2* src = reinterpret_cast<const float2*>(input + grow * KDIM + 10 * h);
            #pragma unroll
            for (int p = 0; p < 5; ++p) v[p] = src[p];
        } else {
            #pragma unroll
            for (int p = 0; p < 5; ++p) v[p] = make_float2(0.f, 0.f);
        }
        uint32_t* row = sW + r * SROW_W;
        #pragma unroll
        for (int p = 0; p < 5; ++p) {
            const int k = 10 * h + 2 * p;
            float x0 = v[p].x, x1 = v[p].y;
            __nv_bfloat16 h0 = __float2bfloat16_rn(x0);
            __nv_bfloat16 h1 = __float2bfloat16_rn(x1);
            uint32_t hp = bf2pack(x0, x1);
            uint32_t lp = bf2pack(x0 - __bfloat162float(h0), x1 - __bfloat162float(h1));
            row[k / 2]      = hp;   // hi block
            row[10 + k / 2] = lp;   // lo block
            row[20 + k / 2] = hp;   // hi dup
        }
        if (h) { row[30] = 0u; row[31] = 0u; }   // k 60..63 = 0
    }
    __syncthreads();

    // ---- main: 8 m16 subtiles ----
    const int colbase = wid * 64 + 2 * cq;

    #pragma unroll 1
    for (int ms = 0; ms < 8; ++ms) {
        const int r0 = 16 * ms + g;

        // A fragments: pa[rr][t] = (A[r0+8rr, 2cq+8t], A[.., +1])
        uint32_t pa[2][8];
        #pragma unroll
        for (int rr = 0; rr < 2; ++rr) {
            const uint32_t* row = sW + (r0 + 8 * rr) * SROW_W + cq;
            #pragma unroll
            for (int t = 0; t < 8; ++t)
                pa[rr][t] = row[4 * t];
        }

        float acc[8][4];
        #pragma unroll
        for (int j = 0; j < 8; ++j) {
            acc[j][0] = acc[j][1] = acc[j][2] = acc[j][3] = 0.f;
        }
        #pragma unroll
        for (int s = 0; s < 4; ++s) {
            #pragma unroll
            for (int j = 0; j < 8; ++j)
                mma16816(acc[j],
                         pa[0][2 * s], pa[1][2 * s], pa[0][2 * s + 1], pa[1][2 * s + 1],
                         Bf[j][2 * s], Bf[j][2 * s + 1]);
        }

        // store: d0d1 -> row (tb+r0), d2d3 -> row (tb+r0+8), cols colbase+8j..+1
        const long long grow0 = tb + r0;
        if (grow0 < batch) {
            float2* p0 = reinterpret_cast<float2*>(out + grow0 * OUT_DIM + colbase);
            #pragma unroll
            for (int j = 0; j < 8; ++j)
                p0[4 * j] = make_float2(acc[j][0], acc[j][1]);
        }
        if (grow0 + 8 < batch) {
            float2* p1 = reinterpret_cast<float2*>(out + (grow0 + 8) * OUT_DIM + colbase);
            #pragma unroll
            for (int j = 0; j < 8; ++j)
                p1[4 * j] = make_float2(acc[j][2], acc[j][3]);
        }
    }
}

// ---------------------------------------------------------------------------
extern "C" void kernel_launch(void* const* d_in, const int* in_sizes, int n_in,
                              void* d_out, int out_size) {
    const float* input  = (const float*)d_in[0];
    const float* weight = (const float*)d_in[1];
    int s0 = in_sizes[0], s1 = in_sizes[1];
    if (s0 < s1) {
        const float* tmp = input; input = weight; weight = tmp;
        int ts = s0; s0 = s1; s1 = ts;
    }
    const int batch  = s0 / KDIM;
    const int ntiles = (batch + TILE_M - 1) / TILE_M;

    qr_kernel<<<1, MROWS>>>(weight);
    gemm_hmma_kernel<<<ntiles, GTHREADS>>>(input, (float*)d_out, batch);
}

// round 7
// speedup vs baseline: 1.2193x; 1.1933x over previous
#include <cuda_runtime.h>
#include <cuda_bf16.h>
#include <cstdint>

#define MROWS   512   // rows of weight / output dim
#define KDIM    20    // motion dim
#define OUT_DIM 512
#define TILE_M  128   // batch rows per tile
#define KPAD    64    // split-K layout: A=[hi20|lo20|hi20|0], B=[hi20|hi20|lo20|0]
#define GTHREADS 256  // 8 warps, each owns 64 output cols
#define SROW_W  36    // smem row stride in words -> conflict-free fragment LDS
#define GRID_P  296   // persistent: 2 CTAs/SM

// B' table (bf16): g_Qbf[n*64 + k]; k 0-19 = Qhi, 20-39 = Qhi, 40-59 = Qlo, 60-63 = 0
__device__ __align__(16) __nv_bfloat16 g_Qbf[OUT_DIM * KPAD];

// ---------------------------------------------------------------------------
// helpers
// ---------------------------------------------------------------------------
__device__ __forceinline__ uint32_t bf2pack(float a, float b) {
    __nv_bfloat162 t = __floats2bfloat162_rn(a, b);
    return *reinterpret_cast<uint32_t*>(&t);
}

__device__ __forceinline__ float blockReduceSum(float x, float* red) {
    int lane = threadIdx.x & 31;
    int wid  = threadIdx.x >> 5;
    #pragma unroll
    for (int off = 16; off; off >>= 1) x += __shfl_xor_sync(0xffffffffu, x, off);
    if (lane == 0) red[wid] = x;
    __syncthreads();
    float s = (lane < 16) ? red[lane] : 0.f;
    #pragma unroll
    for (int off = 8; off; off >>= 1) s += __shfl_xor_sync(0xffffffffu, s, off);
    s = __shfl_sync(0xffffffffu, s, 0);
    __syncthreads();
    return s;
}

__device__ __forceinline__ void mma16816(float* d,
                                         uint32_t a0, uint32_t a1, uint32_t a2, uint32_t a3,
                                         uint32_t b0, uint32_t b1) {
    asm("mma.sync.aligned.m16n8k16.row.col.f32.bf16.bf16.f32 "
        "{%0,%1,%2,%3}, {%4,%5,%6,%7}, {%8,%9}, {%0,%1,%2,%3};"
        : "+f"(d[0]), "+f"(d[1]), "+f"(d[2]), "+f"(d[3])
        : "r"(a0), "r"(a1), "r"(a2), "r"(a3), "r"(b0), "r"(b1));
}

// ---------------------------------------------------------------------------
// Householder QR (LAPACK sgeqr2 + sorg2r) of W + 1e-8, W: [512,20].
// Emits bf16 hi/lo split table g_Qbf (B layout: [qh|qh|ql|0]).
// ---------------------------------------------------------------------------
__global__ void qr_kernel(const float* __restrict__ W) {
    __shared__ float sA[KDIM][MROWS];
    __shared__ float sV[MROWS];
    __shared__ float sTau[KDIM];
    __shared__ float sRed[16];

    const int t    = threadIdx.x;
    const int lane = t & 31;
    const int wid  = t >> 5;

    #pragma unroll
    for (int c = 0; c < KDIM; ++c)
        sA[c][t] = W[t * KDIM + c] + 1e-8f;
    __syncthreads();

    for (int j = 0; j < KDIM; ++j) {
        float a  = sA[j][t];
        float sq = (t > j) ? a * a : 0.f;
        float xnorm2 = blockReduceSum(sq, sRed);
        float alpha  = sA[j][j];
        float beta   = -copysignf(sqrtf(alpha * alpha + xnorm2), alpha);
        float tau    = (beta - alpha) / beta;
        float inv    = 1.f / (alpha - beta);
        float v      = (t == j) ? 1.f : ((t > j) ? a * inv : 0.f);
        sV[t] = v;
        if (t == j)      { sTau[j] = tau; sA[j][j] = beta; }
        else if (t > j)  { sA[j][t] = v; }
        __syncthreads();

        for (int c = j + 1 + wid; c < KDIM; c += 16) {
            float w = 0.f;
            #pragma unroll
            for (int i = lane; i < MROWS; i += 32) w += sV[i] * sA[c][i];
            #pragma unroll
            for (int off = 16; off; off >>= 1) w += __shfl_xor_sync(0xffffffffu, w, off);
            float tw = sTau[j] * w;
            #pragma unroll
            for (int i = lane; i < MROWS; i += 32) sA[c][i] -= tw * sV[i];
        }
        __syncthreads();
    }

    for (int j = KDIM - 1; j >= 0; --j) {
        float tau = sTau[j];
        float vt  = (t == j) ? 1.f : ((t > j) ? sA[j][t] : 0.f);
        sV[t] = vt;
        __syncthreads();

        for (int c = j + 1 + wid; c < KDIM; c += 16) {
            float w = 0.f;
            #pragma unroll
            for (int i = lane; i < MROWS; i += 32) w += sV[i] * sA[c][i];
            #pragma unroll
            for (int off = 16; off; off >>= 1) w += __shfl_xor_sync(0xffffffffu, w, off);
            float tw = tau * w;
            #pragma unroll
            for (int i = lane; i < MROWS; i += 32) sA[c][i] -= tw * sV[i];
        }
        __syncthreads();
        sA[j][t] = (t == j) ? (1.f - tau) : ((t > j) ? -tau * vt : 0.f);
        __syncthreads();
    }

    #pragma unroll
    for (int k = 0; k < KDIM; ++k) {
        float q = sA[k][t];
        __nv_bfloat16 h = __float2bfloat16_rn(q);
        float lo = q - __bfloat162float(h);
        g_Qbf[t * KPAD + k]            = h;
        g_Qbf[t * KPAD + KDIM + k]     = h;
        g_Qbf[t * KPAD + 2 * KDIM + k] = __float2bfloat16_rn(lo);
    }
    #pragma unroll
    for (int k = 3 * KDIM; k < KPAD; ++k)
        g_Qbf[t * KPAD + k] = __float2bfloat16_rn(0.f);
}

// ---------------------------------------------------------------------------
// Persistent HMMA GEMM: out[b][o] = sum_k input[b][k] * Q[o][k]
// 296 blocks grid-stride over M tiles. B fragments gathered ONCE per block
// (register-resident, 64 u32/thread). A tiles double-buffered in smem;
// next tile's convert issues before this tile's MMAs (LDG hides under HMMA).
// ---------------------------------------------------------------------------
__global__ void __launch_bounds__(GTHREADS, 2)
gemm_hmma_kernel(const float* __restrict__ input, float* __restrict__ out,
                 int batch, int ntiles) {
    __shared__ uint32_t sW[2][TILE_M * SROW_W];   // 2 x 18432 B

    const int tid  = threadIdx.x;
    const int wid  = tid >> 5;
    const int lane = tid & 31;
    const int g    = lane >> 2;        // fragment row group 0..7
    const int cq   = lane & 3;         // quad col: k pair base = 2*cq

    // ---- B fragments (once per block): B[j][t] = (B'[2cq+8t, n], B'[+1, n]) ----
    uint32_t Bf[8][8];
    {
        const uint32_t* qw = reinterpret_cast<const uint32_t*>(g_Qbf);
        const int nb = wid * 64 + g;
        #pragma unroll
        for (int j = 0; j < 8; ++j) {
            const uint32_t* qrow = qw + (nb + 8 * j) * (KPAD / 2) + cq;
            #pragma unroll
            for (int t = 0; t < 8; ++t)
                Bf[j][t] = qrow[4 * t];
        }
    }

    // ---- conversion: tile tt -> buffer buf ----
    auto convert_tile = [&](long long tt, int buf) {
        const int r = tid >> 1;                 // row 0..127
        const int h = tid & 1;                  // half: k0 = 10h
        const long long grow = tt * TILE_M + r;
        float2 v[5];
        if (grow < batch) {
            const float2* src = reinterpret_cast<const float2*>(input + grow * KDIM + 10 * h);
            #pragma unroll
            for (int p = 0; p < 5; ++p) v[p] = src[p];
        } else {
            #pragma unroll
            for (int p = 0; p < 5; ++p) v[p] = make_float2(0.f, 0.f);
        }
        uint32_t* row = sW[buf] + r * SROW_W;
        #pragma unroll
        for (int p = 0; p < 5; ++p) {
            const int k = 10 * h + 2 * p;
            float x0 = v[p].x, x1 = v[p].y;
            __nv_bfloat16 h0 = __float2bfloat16_rn(x0);
            __nv_bfloat16 h1 = __float2bfloat16_rn(x1);
            uint32_t hp = bf2pack(x0, x1);
            uint32_t lp = bf2pack(x0 - __bfloat162float(h0), x1 - __bfloat162float(h1));
            row[k / 2]      = hp;   // hi block
            row[10 + k / 2] = lp;   // lo block
            row[20 + k / 2] = hp;   // hi dup
        }
        if (h) { row[30] = 0u; row[31] = 0u; }   // k 60..63 = 0
    };

    const int colbase = wid * 64 + 2 * cq;
    const long long stride = gridDim.x;
    const long long t0 = blockIdx.x;

    if (t0 < ntiles) convert_tile(t0, 0);
    __syncthreads();

    int buf = 0;
    for (long long t = t0; t < ntiles; t += stride) {
        // prefetch-convert next tile into the other buffer (overlaps MMAs below)
        const long long tn = t + stride;
        if (tn < ntiles) convert_tile(tn, buf ^ 1);

        const long long tb = t * TILE_M;

        #pragma unroll 1
        for (int ms = 0; ms < 8; ++ms) {
            const int r0 = 16 * ms + g;

            uint32_t pa[2][8];
            #pragma unroll
            for (int rr = 0; rr < 2; ++rr) {
                const uint32_t* row = sW[buf] + (r0 + 8 * rr) * SROW_W + cq;
                #pragma unroll
                for (int tt = 0; tt < 8; ++tt)
                    pa[rr][tt] = row[4 * tt];
            }

            float acc[8][4];
            #pragma unroll
            for (int j = 0; j < 8; ++j)
                acc[j][0] = acc[j][1] = acc[j][2] = acc[j][3] = 0.f;

            #pragma unroll
            for (int s = 0; s < 4; ++s) {
                #pragma unroll
                for (int j = 0; j < 8; ++j)
                    mma16816(acc[j],
                             pa[0][2 * s], pa[1][2 * s], pa[0][2 * s + 1], pa[1][2 * s + 1],
                             Bf[j][2 * s], Bf[j][2 * s + 1]);
            }

            const long long grow0 = tb + r0;
            if (grow0 < batch) {
                float2* p0 = reinterpret_cast<float2*>(out + grow0 * OUT_DIM + colbase);
                #pragma unroll
                for (int j = 0; j < 8; ++j)
                    p0[4 * j] = make_float2(acc[j][0], acc[j][1]);
            }
            if (grow0 + 8 < batch) {
                float2* p1 = reinterpret_cast<float2*>(out + (grow0 + 8) * OUT_DIM + colbase);
                #pragma unroll
                for (int j = 0; j < 8; ++j)
                    p1[4 * j] = make_float2(acc[j][2], acc[j][3]);
            }
        }

        __syncthreads();   // next buffer fully written; old buffer free
        buf ^= 1;
    }
}

// ---------------------------------------------------------------------------
extern "C" void kernel_launch(void* const* d_in, const int* in_sizes, int n_in,
                              void* d_out, int out_size) {
    const float* input  = (const float*)d_in[0];
    const float* weight = (const float*)d_in[1];
    int s0 = in_sizes[0], s1 = in_sizes[1];
    if (s0 < s1) {
        const float* tmp = input; input = weight; weight = tmp;
        int ts = s0; s0 = s1; s1 = ts;
    }
    const int batch  = s0 / KDIM;
    const int ntiles = (batch + TILE_M - 1) / TILE_M;

    qr_kernel<<<1, MROWS>>>(weight);
    gemm_hmma_kernel<<<GRID_P, GTHREADS>>>(input, (float*)d_out, batch, ntiles);
}

// round 8
// speedup vs baseline: 1.2744x; 1.0452x over previous
#include <cuda_runtime.h>
#include <cuda_bf16.h>
#include <cstdint>

#define MROWS   512   // rows of weight / output dim
#define KDIM    20    // motion dim
#define OUT_DIM 512
#define TILE_M  128   // batch rows per tile
#define KPAD    64    // split-K layout: A=[hi20|lo20|hi20|0], B=[hi20|hi20|lo20|0]
#define GTHREADS 256  // 8 warps, each owns 64 output cols
#define SROW_W  36    // smem row stride in words -> conflict-free LDSM phases
#define GRID_P  296   // persistent: 2 CTAs/SM

// B' table (bf16): g_Qbf[n*64 + k]; k 0-19 = Qhi, 20-39 = Qhi, 40-59 = Qlo, 60-63 = 0
__device__ __align__(16) __nv_bfloat16 g_Qbf[OUT_DIM * KPAD];

// ---------------------------------------------------------------------------
// helpers
// ---------------------------------------------------------------------------
__device__ __forceinline__ uint32_t bf2pack(float a, float b) {
    __nv_bfloat162 t = __floats2bfloat162_rn(a, b);
    return *reinterpret_cast<uint32_t*>(&t);
}

__device__ __forceinline__ float blockReduceSum(float x, float* red) {
    int lane = threadIdx.x & 31;
    int wid  = threadIdx.x >> 5;
    #pragma unroll
    for (int off = 16; off; off >>= 1) x += __shfl_xor_sync(0xffffffffu, x, off);
    if (lane == 0) red[wid] = x;
    __syncthreads();
    float s = (lane < 16) ? red[lane] : 0.f;
    #pragma unroll
    for (int off = 8; off; off >>= 1) s += __shfl_xor_sync(0xffffffffu, s, off);
    s = __shfl_sync(0xffffffffu, s, 0);
    __syncthreads();
    return s;
}

__device__ __forceinline__ void mma16816(float* d,
                                         uint32_t a0, uint32_t a1, uint32_t a2, uint32_t a3,
                                         uint32_t b0, uint32_t b1) {
    asm("mma.sync.aligned.m16n8k16.row.col.f32.bf16.bf16.f32 "
        "{%0,%1,%2,%3}, {%4,%5,%6,%7}, {%8,%9}, {%0,%1,%2,%3};"
        : "+f"(d[0]), "+f"(d[1]), "+f"(d[2]), "+f"(d[3])
        : "r"(a0), "r"(a1), "r"(a2), "r"(a3), "r"(b0), "r"(b1));
}

__device__ __forceinline__ void ldsm_x4(uint32_t* r, uint32_t addr) {
    asm volatile("ldmatrix.sync.aligned.m8n8.x4.shared.b16 {%0,%1,%2,%3}, [%4];"
                 : "=r"(r[0]), "=r"(r[1]), "=r"(r[2]), "=r"(r[3]) : "r"(addr));
}

__device__ __forceinline__ void stg_cs_v2(float* p, float x, float y) {
    asm volatile("st.global.cs.v2.f32 [%0], {%1, %2};" :: "l"(p), "f"(x), "f"(y) : "memory");
}

// ---------------------------------------------------------------------------
// Householder QR (LAPACK sgeqr2 + sorg2r) of W + 1e-8, W: [512,20].
// Emits bf16 hi/lo split table g_Qbf (B layout: [qh|qh|ql|0]).
// ---------------------------------------------------------------------------
__global__ void qr_kernel(const float* __restrict__ W) {
    __shared__ float sA[KDIM][MROWS];
    __shared__ float sV[MROWS];
    __shared__ float sTau[KDIM];
    __shared__ float sRed[16];

    const int t    = threadIdx.x;
    const int lane = t & 31;
    const int wid  = t >> 5;

    #pragma unroll
    for (int c = 0; c < KDIM; ++c)
        sA[c][t] = W[t * KDIM + c] + 1e-8f;
    __syncthreads();

    for (int j = 0; j < KDIM; ++j) {
        float a  = sA[j][t];
        float sq = (t > j) ? a * a : 0.f;
        float xnorm2 = blockReduceSum(sq, sRed);
        float alpha  = sA[j][j];
        float beta   = -copysignf(sqrtf(alpha * alpha + xnorm2), alpha);
        float tau    = (beta - alpha) / beta;
        float inv    = 1.f / (alpha - beta);
        float v      = (t == j) ? 1.f : ((t > j) ? a * inv : 0.f);
        sV[t] = v;
        if (t == j)      { sTau[j] = tau; sA[j][j] = beta; }
        else if (t > j)  { sA[j][t] = v; }
        __syncthreads();

        for (int c = j + 1 + wid; c < KDIM; c += 16) {
            float w = 0.f;
            #pragma unroll
            for (int i = lane; i < MROWS; i += 32) w += sV[i] * sA[c][i];
            #pragma unroll
            for (int off = 16; off; off >>= 1) w += __shfl_xor_sync(0xffffffffu, w, off);
            float tw = sTau[j] * w;
            #pragma unroll
            for (int i = lane; i < MROWS; i += 32) sA[c][i] -= tw * sV[i];
        }
        __syncthreads();
    }

    for (int j = KDIM - 1; j >= 0; --j) {
        float tau = sTau[j];
        float vt  = (t == j) ? 1.f : ((t > j) ? sA[j][t] : 0.f);
        sV[t] = vt;
        __syncthreads();

        for (int c = j + 1 + wid; c < KDIM; c += 16) {
            float w = 0.f;
            #pragma unroll
            for (int i = lane; i < MROWS; i += 32) w += sV[i] * sA[c][i];
            #pragma unroll
            for (int off = 16; off; off >>= 1) w += __shfl_xor_sync(0xffffffffu, w, off);
            float tw = tau * w;
            #pragma unroll
            for (int i = lane; i < MROWS; i += 32) sA[c][i] -= tw * sV[i];
        }
        __syncthreads();
        sA[j][t] = (t == j) ? (1.f - tau) : ((t > j) ? -tau * vt : 0.f);
        __syncthreads();
    }

    #pragma unroll
    for (int k = 0; k < KDIM; ++k) {
        float q = sA[k][t];
        __nv_bfloat16 h = __float2bfloat16_rn(q);
        float lo = q - __bfloat162float(h);
        g_Qbf[t * KPAD + k]            = h;
        g_Qbf[t * KPAD + KDIM + k]     = h;
        g_Qbf[t * KPAD + 2 * KDIM + k] = __float2bfloat16_rn(lo);
    }
    #pragma unroll
    for (int k = 3 * KDIM; k < KPAD; ++k)
        g_Qbf[t * KPAD + k] = __float2bfloat16_rn(0.f);
}

// ---------------------------------------------------------------------------
// Persistent HMMA GEMM: out[b][o] = sum_k input[b][k] * Q[o][k]
// 296 blocks grid-stride over M tiles. B fragments register-resident (once
// per block). A tiles double-buffered; A fragments via ldmatrix.x4 (4 instr
// per subtile instead of 16 LDS.32). Output stores use st.global.cs.
// ---------------------------------------------------------------------------
__global__ void __launch_bounds__(GTHREADS, 2)
gemm_hmma_kernel(const float* __restrict__ input, float* __restrict__ out,
                 int batch, int ntiles) {
    __shared__ uint32_t sW[2][TILE_M * SROW_W];   // 2 x 18432 B

    const int tid  = threadIdx.x;
    const int wid  = tid >> 5;
    const int lane = tid & 31;
    const int g    = lane >> 2;        // fragment row group 0..7
    const int cq   = lane & 3;         // quad col: k pair base = 2*cq

    // ---- B fragments (once per block): B[j][t] = (B'[2cq+8t, n], B'[+1, n]) ----
    uint32_t Bf[8][8];
    {
        const uint32_t* qw = reinterpret_cast<const uint32_t*>(g_Qbf);
        const int nb = wid * 64 + g;
        #pragma unroll
        for (int j = 0; j < 8; ++j) {
            const uint32_t* qrow = qw + (nb + 8 * j) * (KPAD / 2) + cq;
            #pragma unroll
            for (int t = 0; t < 8; ++t)
                Bf[j][t] = qrow[4 * t];
        }
    }

    // ---- conversion: tile tt -> buffer buf ----
    auto convert_tile = [&](long long tt, int buf) {
        const int r = tid >> 1;                 // row 0..127
        const int h = tid & 1;                  // half: k0 = 10h
        const long long grow = tt * TILE_M + r;
        float2 v[5];
        if (grow < batch) {
            const float2* src = reinterpret_cast<const float2*>(input + grow * KDIM + 10 * h);
            #pragma unroll
            for (int p = 0; p < 5; ++p) v[p] = src[p];
        } else {
            #pragma unroll
            for (int p = 0; p < 5; ++p) v[p] = make_float2(0.f, 0.f);
        }
        uint32_t* row = sW[buf] + r * SROW_W;
        #pragma unroll
        for (int p = 0; p < 5; ++p) {
            const int k = 10 * h + 2 * p;
            float x0 = v[p].x, x1 = v[p].y;
            __nv_bfloat16 h0 = __float2bfloat16_rn(x0);
            __nv_bfloat16 h1 = __float2bfloat16_rn(x1);
            uint32_t hp = bf2pack(x0, x1);
            uint32_t lp = bf2pack(x0 - __bfloat162float(h0), x1 - __bfloat162float(h1));
            row[k / 2]      = hp;   // hi block
            row[10 + k / 2] = lp;   // lo block
            row[20 + k / 2] = hp;   // hi dup
        }
        if (h) { row[30] = 0u; row[31] = 0u; }   // k 60..63 = 0
    };

    // ldmatrix lane address base: row = (lane&15), k-half = (lane&16)?8..15
    const uint32_t smem0 = (uint32_t)__cvta_generic_to_shared(&sW[0][0]);
    const uint32_t smem1 = (uint32_t)__cvta_generic_to_shared(&sW[1][0]);
    const uint32_t lane_off = (((lane & 15) * SROW_W + ((lane & 16) ? 4 : 0)) * 4);

    const int colbase = wid * 64 + 2 * cq;
    const long long stride = gridDim.x;
    const long long t0 = blockIdx.x;

    if (t0 < ntiles) convert_tile(t0, 0);
    __syncthreads();

    int buf = 0;
    for (long long t = t0; t < ntiles; t += stride) {
        // prefetch-convert next tile into the other buffer (overlaps MMAs below)
        const long long tn = t + stride;
        if (tn < ntiles) convert_tile(tn, buf ^ 1);

        const long long tb = t * TILE_M;
        const uint32_t sbase = (buf ? smem1 : smem0) + lane_off;

        #pragma unroll 1
        for (int ms = 0; ms < 8; ++ms) {
            const uint32_t mbase = sbase + (uint32_t)(16 * ms * SROW_W * 4);

            float acc[8][4];
            #pragma unroll
            for (int j = 0; j < 8; ++j)
                acc[j][0] = acc[j][1] = acc[j][2] = acc[j][3] = 0.f;

            #pragma unroll
            for (int s = 0; s < 4; ++s) {
                uint32_t a[4];
                ldsm_x4(a, mbase + 32u * s);   // 8 words per k16 chunk
                #pragma unroll
                for (int j = 0; j < 8; ++j)
                    mma16816(acc[j], a[0], a[1], a[2], a[3],
                             Bf[j][2 * s], Bf[j][2 * s + 1]);
            }

            const long long grow0 = tb + 16 * ms + g;
            if (grow0 < batch) {
                float* p0 = out + grow0 * OUT_DIM + colbase;
                #pragma unroll
                for (int j = 0; j < 8; ++j)
                    stg_cs_v2(p0 + 8 * j, acc[j][0], acc[j][1]);
            }
            if (grow0 + 8 < batch) {
                float* p1 = out + (grow0 + 8) * OUT_DIM + colbase;
                #pragma unroll
                for (int j = 0; j < 8; ++j)
                    stg_cs_v2(p1 + 8 * j, acc[j][2], acc[j][3]);
            }
        }

        __syncthreads();   // next buffer fully written; old buffer free
        buf ^= 1;
    }
}

// ---------------------------------------------------------------------------
extern "C" void kernel_launch(void* const* d_in, const int* in_sizes, int n_in,
                              void* d_out, int out_size) {
    const float* input  = (const float*)d_in[0];
    const float* weight = (const float*)d_in[1];
    int s0 = in_sizes[0], s1 = in_sizes[1];
    if (s0 < s1) {
        const float* tmp = input; input = weight; weight = tmp;
        int ts = s0; s0 = s1; s1 = ts;
    }
    const int batch  = s0 / KDIM;
    const int ntiles = (batch + TILE_M - 1) / TILE_M;

    qr_kernel<<<1, MROWS>>>(weight);
    gemm_hmma_kernel<<<GRID_P, GTHREADS>>>(input, (float*)d_out, batch, ntiles);
}